// round 1
// baseline (speedup 1.0000x reference)
#include <cuda_runtime.h>
#include <stdint.h>

#define NN 100000
#define EE 3200000
#define TT 8
#define FF 64

// ---------------- device scratch (allocation-free) ----------------
__device__ float g_y[(size_t)TT * NN * FF];   // 204.8 MB: y[t*N+n][f]
__device__ float g_hacc[(size_t)NN * FF];     // 25.6 MB, zero-init, kept zeroed
__device__ float g_h1[(size_t)NN * FF];       // 25.6 MB
__device__ float g_V1[64 * 512];              // permuted W1: V[fin][t*64+fout]
__device__ float g_V2[64 * 512];
__device__ int   g_gidx[EE];                  // t*N + src
__device__ int   g_dst[EE];
__device__ int   g_mode;                      // 1 = indices are int64, 0 = int32

// ---------------- dtype detection ----------------
// If edge_index is int64 (values < 2^31), every odd int32 word is 0.
__global__ void k_detect(const int* __restrict__ ei) {
    __shared__ int any_nonzero;
    if (threadIdx.x == 0) any_nonzero = 0;
    __syncthreads();
    int v = ei[2 * threadIdx.x + 1];
    if (v != 0) atomicExch(&any_nonzero, 1);
    __syncthreads();
    if (threadIdx.x == 0) g_mode = (any_nonzero == 0) ? 1 : 0;
}

// ---------------- edge prep: g_gidx = t*N+src, g_dst ----------------
__global__ void k_prep_edges(const void* __restrict__ ei_raw,
                             const void* __restrict__ ti_raw) {
    int e = blockIdx.x * blockDim.x + threadIdx.x;
    if (e >= EE) return;
    int src, dst, t;
    if (g_mode) {
        const long long* ei = (const long long*)ei_raw;
        const long long* ti = (const long long*)ti_raw;
        src = (int)ei[e];
        dst = (int)ei[(size_t)EE + e];
        t   = (int)ti[e];
    } else {
        const int* ei = (const int*)ei_raw;
        const int* ti = (const int*)ti_raw;
        src = ei[e];
        dst = ei[EE + e];
        t   = ti[e];
    }
    g_gidx[e] = t * NN + src;
    g_dst[e]  = dst;
}

// ---------------- weight permute: V[fin*512 + t*64+fo] = W[(t*64+fin)*64+fo] ----
__global__ void k_prep_w(const float* __restrict__ W, float* __restrict__ V) {
    int idx = blockIdx.x * blockDim.x + threadIdx.x;   // < 32768
    int fin = idx >> 9;
    int j   = idx & 511;
    int t   = j >> 6;
    int fo  = j & 63;
    V[idx] = W[((t << 6) + fin) * 64 + fo];
}

// ---------------- y[t*N+n][:] = in[n][:] @ W_t  (per-t 64x64) ----------------
// block: 128 threads = 32 (j-lane) x 4 (node-group); 16 nodes per block.
__global__ void __launch_bounds__(128) k_gemm(const float* __restrict__ in,
                                              const float* __restrict__ V,
                                              float* __restrict__ y) {
    __shared__ float xs[16][64];
    int tid = threadIdx.x;
    int nb  = blockIdx.x * 16;

    // stage 16 node rows (1024 floats) as float4
    {
        const float4* inv = (const float4*)(in + (size_t)nb * 64);
        float4* xsv = (float4*)&xs[0][0];
        xsv[tid]       = inv[tid];
        xsv[tid + 128] = inv[tid + 128];
    }
    __syncthreads();

    int jt = tid & 31;   // j4 lane
    int ng = tid >> 5;   // node group (4 nodes each)

    float4 acc[4][4];
#pragma unroll
    for (int i = 0; i < 4; i++)
#pragma unroll
        for (int s = 0; s < 4; s++) acc[i][s] = make_float4(0.f, 0.f, 0.f, 0.f);

    const float4* Vr = (const float4*)V;   // [64][128]

#pragma unroll 4
    for (int fin = 0; fin < 64; ++fin) {
        float xv[4];
#pragma unroll
        for (int i = 0; i < 4; i++) xv[i] = xs[(ng << 2) + i][fin];
#pragma unroll
        for (int s = 0; s < 4; s++) {
            float4 w = __ldg(&Vr[fin * 128 + jt + s * 32]);
#pragma unroll
            for (int i = 0; i < 4; i++) {
                acc[i][s].x += xv[i] * w.x;
                acc[i][s].y += xv[i] * w.y;
                acc[i][s].z += xv[i] * w.z;
                acc[i][s].w += xv[i] * w.w;
            }
        }
    }

    float4* yv = (float4*)y;
#pragma unroll
    for (int s = 0; s < 4; s++) {
        int j4 = jt + s * 32;           // 0..127
        int t  = j4 >> 4;               // which time block
        int c4 = j4 & 15;               // float4 col within row
#pragma unroll
        for (int i = 0; i < 4; i++) {
            int node = nb + (ng << 2) + i;
            yv[(size_t)(t * NN + node) * 16 + c4] = acc[i][s];
        }
    }
}

// ---------------- scatter: hacc[dst] += y[t*N+src]  (float4 atomics) --------
__global__ void __launch_bounds__(256) k_scatter(void) {
    size_t idx = (size_t)blockIdx.x * 256 + threadIdx.x;   // < E*16
    int e = (int)(idx >> 4);
    int c = (int)(idx & 15);
    int row = __ldg(&g_gidx[e]);
    int d   = __ldg(&g_dst[e]);
    const float4* yv = (const float4*)g_y;
    float4 v = __ldg(&yv[(size_t)row * 16 + c]);
    float4* hv = (float4*)g_hacc;
    atomicAdd(&hv[(size_t)d * 16 + c], v);
}

// ---------------- epilogue: out = relu(hacc + b); hacc = 0 ----------------
__global__ void __launch_bounds__(256) k_bias_relu_reset(const float* __restrict__ bias,
                                                         float* __restrict__ out) {
    int i = blockIdx.x * 256 + threadIdx.x;   // < N*16
    float4* hv = (float4*)g_hacc;
    float4 v = hv[i];
    hv[i] = make_float4(0.f, 0.f, 0.f, 0.f);
    float4 b = __ldg(&((const float4*)bias)[i & 15]);
    float4 r;
    r.x = fmaxf(v.x + b.x, 0.f);
    r.y = fmaxf(v.y + b.y, 0.f);
    r.z = fmaxf(v.z + b.z, 0.f);
    r.w = fmaxf(v.w + b.w, 0.f);
    ((float4*)out)[i] = r;
}

// ---------------- ssl = h2 @ Wssl + bssl ----------------
// block 256 = 4 nodes x 64 fout
__global__ void __launch_bounds__(256) k_ssl(const float* __restrict__ h2,
                                             const float* __restrict__ Wssl,
                                             const float* __restrict__ bssl,
                                             float* __restrict__ out) {
    __shared__ float ws[64 * 64];
    __shared__ float hs[4 * 64];
    int tid = threadIdx.x;
    int nb  = blockIdx.x * 4;

    {
        float4* wsv = (float4*)ws;
        const float4* Wv = (const float4*)Wssl;
#pragma unroll
        for (int k = 0; k < 4; k++) wsv[tid + k * 256] = Wv[tid + k * 256];
        hs[tid] = h2[(size_t)nb * 64 + tid];
    }
    __syncthreads();

    int nl = tid >> 6;
    int fo = tid & 63;
    float a = __ldg(&bssl[fo]);
#pragma unroll 8
    for (int fin = 0; fin < 64; ++fin)
        a += hs[nl * 64 + fin] * ws[fin * 64 + fo];
    out[(size_t)(nb + nl) * 64 + fo] = a;
}

// ---------------- launch ----------------
extern "C" void kernel_launch(void* const* d_in, const int* in_sizes, int n_in,
                              void* d_out, int out_size) {
    const float* x    = (const float*)d_in[0];
    const void*  ei   = d_in[1];
    const void*  ti   = d_in[2];
    const float* W1   = (const float*)d_in[3];
    const float* b1   = (const float*)d_in[4];
    const float* W2   = (const float*)d_in[5];
    const float* b2   = (const float*)d_in[6];
    const float* Wssl = (const float*)d_in[7];
    const float* bssl = (const float*)d_in[8];
    float* out_h   = (float*)d_out;                     // first N*64: h
    float* out_ssl = (float*)d_out + (size_t)NN * 64;   // second N*64: ssl

    float* dV1;  cudaGetSymbolAddress((void**)&dV1, g_V1);
    float* dV2;  cudaGetSymbolAddress((void**)&dV2, g_V2);
    float* dy;   cudaGetSymbolAddress((void**)&dy, g_y);
    float* dh1;  cudaGetSymbolAddress((void**)&dh1, g_h1);

    k_detect<<<1, 256>>>((const int*)ei);
    k_prep_edges<<<EE / 256, 256>>>(ei, ti);
    k_prep_w<<<32768 / 256, 256>>>(W1, dV1);
    k_prep_w<<<32768 / 256, 256>>>(W2, dV2);

    // layer 1
    k_gemm<<<NN / 16, 128>>>(x, dV1, dy);
    k_scatter<<<(EE * 16) / 256, 256>>>();
    k_bias_relu_reset<<<(NN * 16) / 256, 256>>>(b1, dh1);

    // layer 2
    k_gemm<<<NN / 16, 128>>>(dh1, dV2, dy);
    k_scatter<<<(EE * 16) / 256, 256>>>();
    k_bias_relu_reset<<<(NN * 16) / 256, 256>>>(b2, out_h);

    // ssl head
    k_ssl<<<NN / 4, 256>>>(out_h, Wssl, bssl, out_ssl);
}

// round 2
// speedup vs baseline: 1.0878x; 1.0878x over previous
#include <cuda_runtime.h>
#include <stdint.h>

#define NN 100000
#define EE 3200000
#define TT 8
#define FF 64

// ---------------- device scratch (allocation-free) ----------------
__device__ float g_y[(size_t)TT * NN * FF];   // 204.8 MB: y[t*N+n][f]
__device__ float g_hacc[(size_t)NN * FF];     // 25.6 MB, zero-init, kept zeroed
__device__ float g_h1[(size_t)NN * FF];       // 25.6 MB
__device__ float g_V1[64 * 512];              // permuted W1: V[fin][t*64+fout]
__device__ float g_V2[64 * 512];
__device__ int2  g_edge[EE];                  // {t*N+src, dst}
__device__ int   g_mode;                      // 1 = indices are int64, 0 = int32

// ---------------- dtype detection ----------------
__global__ void k_detect(const int* __restrict__ ei) {
    __shared__ int any_nonzero;
    if (threadIdx.x == 0) any_nonzero = 0;
    __syncthreads();
    int v = ei[2 * threadIdx.x + 1];
    if (v != 0) atomicExch(&any_nonzero, 1);
    __syncthreads();
    if (threadIdx.x == 0) g_mode = (any_nonzero == 0) ? 1 : 0;
}

// ---------------- edge prep ----------------
__global__ void k_prep_edges(const void* __restrict__ ei_raw,
                             const void* __restrict__ ti_raw) {
    int e = blockIdx.x * blockDim.x + threadIdx.x;
    if (e >= EE) return;
    int src, dst, t;
    if (g_mode) {
        const long long* ei = (const long long*)ei_raw;
        const long long* ti = (const long long*)ti_raw;
        src = (int)ei[e];
        dst = (int)ei[(size_t)EE + e];
        t   = (int)ti[e];
    } else {
        const int* ei = (const int*)ei_raw;
        const int* ti = (const int*)ti_raw;
        src = ei[e];
        dst = ei[EE + e];
        t   = ti[e];
    }
    g_edge[e] = make_int2(t * NN + src, dst);
}

// ---------------- weight permute ----------------
__global__ void k_prep_w(const float* __restrict__ W, float* __restrict__ V) {
    int idx = blockIdx.x * blockDim.x + threadIdx.x;   // < 32768
    int fin = idx >> 9;
    int j   = idx & 511;
    int t   = j >> 6;
    int fo  = j & 63;
    V[idx] = W[((t << 6) + fin) * 64 + fo];
}

// ---------------- y[t*N+n][:] = in[n][:] @ W_t  (f32x2 packed FMA) ----------
// block: 128 threads = 32 (j4-lane) x 4 (node-group); 16 nodes per block.
__global__ void __launch_bounds__(128) k_gemm(const float* __restrict__ in,
                                              const float* __restrict__ V,
                                              float* __restrict__ y) {
    __shared__ float xs[16][64];
    int tid = threadIdx.x;
    int nb  = blockIdx.x * 16;

    {
        const float4* inv = (const float4*)(in + (size_t)nb * 64);
        float4* xsv = (float4*)&xs[0][0];
        xsv[tid]       = inv[tid];
        xsv[tid + 128] = inv[tid + 128];
    }
    __syncthreads();

    int jt = tid & 31;   // float4 column lane
    int ng = tid >> 5;   // node group (4 nodes each)

    // acc[i][s][h]: node i, col-group s, half h (2 packed fp32 each)
    unsigned long long acc[4][4][2];
#pragma unroll
    for (int i = 0; i < 4; i++)
#pragma unroll
        for (int s = 0; s < 4; s++) { acc[i][s][0] = 0ull; acc[i][s][1] = 0ull; }

    const ulonglong2* Vr = (const ulonglong2*)V;   // rows of 128 float4

#pragma unroll 4
    for (int fin = 0; fin < 64; ++fin) {
        unsigned long long xv[4];
#pragma unroll
        for (int i = 0; i < 4; i++) {
            unsigned int xb = __float_as_uint(xs[(ng << 2) + i][fin]);
            asm("mov.b64 %0, {%1, %1};" : "=l"(xv[i]) : "r"(xb));
        }
#pragma unroll
        for (int s = 0; s < 4; s++) {
            ulonglong2 w = __ldg(&Vr[fin * 128 + jt + s * 32]);
#pragma unroll
            for (int i = 0; i < 4; i++) {
                asm("fma.rn.f32x2 %0, %1, %2, %0;"
                    : "+l"(acc[i][s][0]) : "l"(xv[i]), "l"(w.x));
                asm("fma.rn.f32x2 %0, %1, %2, %0;"
                    : "+l"(acc[i][s][1]) : "l"(xv[i]), "l"(w.y));
            }
        }
    }

    ulonglong2* yv = (ulonglong2*)y;
#pragma unroll
    for (int s = 0; s < 4; s++) {
        int j4 = jt + s * 32;           // 0..127
        int t  = j4 >> 4;
        int c4 = j4 & 15;
#pragma unroll
        for (int i = 0; i < 4; i++) {
            int node = nb + (ng << 2) + i;
            ulonglong2 o;
            o.x = acc[i][s][0];
            o.y = acc[i][s][1];
            yv[(size_t)(t * NN + node) * 16 + c4] = o;
        }
    }
}

// ---------------- scatter: hacc[dst] += y[t*N+src]  (float4 atomics) --------
__global__ void __launch_bounds__(256) k_scatter(void) {
    size_t idx = (size_t)blockIdx.x * 256 + threadIdx.x;   // < E*16
    int e = (int)(idx >> 4);
    int c = (int)(idx & 15);
    int2 ed = __ldg(&g_edge[e]);
    const float4* yv = (const float4*)g_y;
    float4 v = __ldg(&yv[(size_t)ed.x * 16 + c]);
    float4* hv = (float4*)g_hacc;
    atomicAdd(&hv[(size_t)ed.y * 16 + c], v);
}

// ---------------- epilogue: out = relu(hacc + b); hacc = 0 ----------------
__global__ void __launch_bounds__(256) k_bias_relu_reset(const float* __restrict__ bias,
                                                         float* __restrict__ out) {
    int i = blockIdx.x * 256 + threadIdx.x;   // < N*16
    float4* hv = (float4*)g_hacc;
    float4 v = hv[i];
    hv[i] = make_float4(0.f, 0.f, 0.f, 0.f);
    float4 b = __ldg(&((const float4*)bias)[i & 15]);
    float4 r;
    r.x = fmaxf(v.x + b.x, 0.f);
    r.y = fmaxf(v.y + b.y, 0.f);
    r.z = fmaxf(v.z + b.z, 0.f);
    r.w = fmaxf(v.w + b.w, 0.f);
    ((float4*)out)[i] = r;
}

// ---------------- ssl = h2 @ Wssl + bssl ----------------
__global__ void __launch_bounds__(256) k_ssl(const float* __restrict__ h2,
                                             const float* __restrict__ Wssl,
                                             const float* __restrict__ bssl,
                                             float* __restrict__ out) {
    __shared__ float ws[64 * 64];
    __shared__ float hs[4 * 64];
    int tid = threadIdx.x;
    int nb  = blockIdx.x * 4;

    {
        float4* wsv = (float4*)ws;
        const float4* Wv = (const float4*)Wssl;
#pragma unroll
        for (int k = 0; k < 4; k++) wsv[tid + k * 256] = Wv[tid + k * 256];
        hs[tid] = h2[(size_t)nb * 64 + tid];
    }
    __syncthreads();

    int nl = tid >> 6;
    int fo = tid & 63;
    float a = __ldg(&bssl[fo]);
#pragma unroll 8
    for (int fin = 0; fin < 64; ++fin)
        a += hs[nl * 64 + fin] * ws[fin * 64 + fo];
    out[(size_t)(nb + nl) * 64 + fo] = a;
}

// ---------------- launch ----------------
extern "C" void kernel_launch(void* const* d_in, const int* in_sizes, int n_in,
                              void* d_out, int out_size) {
    const float* x    = (const float*)d_in[0];
    const void*  ei   = d_in[1];
    const void*  ti   = d_in[2];
    const float* W1   = (const float*)d_in[3];
    const float* b1   = (const float*)d_in[4];
    const float* W2   = (const float*)d_in[5];
    const float* b2   = (const float*)d_in[6];
    const float* Wssl = (const float*)d_in[7];
    const float* bssl = (const float*)d_in[8];
    float* out_h   = (float*)d_out;
    float* out_ssl = (float*)d_out + (size_t)NN * 64;

    float* dV1;  cudaGetSymbolAddress((void**)&dV1, g_V1);
    float* dV2;  cudaGetSymbolAddress((void**)&dV2, g_V2);
    float* dy;   cudaGetSymbolAddress((void**)&dy, g_y);
    float* dh1;  cudaGetSymbolAddress((void**)&dh1, g_h1);

    k_detect<<<1, 256>>>((const int*)ei);
    k_prep_edges<<<EE / 256, 256>>>(ei, ti);
    k_prep_w<<<32768 / 256, 256>>>(W1, dV1);
    k_prep_w<<<32768 / 256, 256>>>(W2, dV2);

    // layer 1
    k_gemm<<<NN / 16, 128>>>(x, dV1, dy);
    k_scatter<<<(EE * 16) / 256, 256>>>();
    k_bias_relu_reset<<<(NN * 16) / 256, 256>>>(b1, dh1);

    // layer 2
    k_gemm<<<NN / 16, 128>>>(dh1, dV2, dy);
    k_scatter<<<(EE * 16) / 256, 256>>>();
    k_bias_relu_reset<<<(NN * 16) / 256, 256>>>(b2, out_h);

    // ssl head
    k_ssl<<<NN / 4, 256>>>(out_h, Wssl, bssl, out_ssl);
}